// round 11
// baseline (speedup 1.0000x reference)
#include <cuda_runtime.h>
#include <math.h>

#define NL 4
#define H  1024
#define E  2048
#define G3 3072
#define OUTN 50257
#define GI_ROWS (2 * G3)          // 6144 rows per layer
#define GH_UNITS (NL * GI_ROWS)   // 24576 rows total

// Persistent scratch (__device__ globals; no allocation in kernel_launch).
__device__ float g_x[E];            // current layer input (E = 2H)
__device__ float g_gi[GI_ROWS];     // W_ih @ x + b_ih  (current layer)
__device__ float g_ghA[GH_UNITS];   // W_hh @ h + b_hh  (ALL layers)

__device__ __forceinline__ float sigmoidf(float x) {
    return 1.0f / (1.0f + expf(-x));
}

__device__ __forceinline__ void pdl_wait() {
    asm volatile("griddepcontrol.wait;" ::: "memory");
}

// ---------------------------------------------------------------------------
// gi: W_ih[l] GEMV.  512-thread block = two 256-thread row teams
// (R10-proven pattern: front-batched float4, x straight from global/L2).
// grid = 3072.  Layer 0 reads x from the embedding table (fused embed).
// ---------------------------------------------------------------------------
__global__ void __launch_bounds__(512) gi_kernel(
    const float* __restrict__ wih, const float* __restrict__ bih,
    const float* __restrict__ table, const int* __restrict__ feat, int l) {

    pdl_wait();

    int half = threadIdx.x >> 8;     // which of the 2 rows
    int t    = threadIdx.x & 255;

    int row = blockIdx.x * 2 + half; // 0 .. 6143
    int d = (row >= G3) ? 1 : 0;     // both rows share d (G3 even)
    int j = row - d * G3;

    const float4* wi = (const float4*)(wih + ((size_t)(l * 2 + d) * G3 + j) * E);
    const float4* xv = (l == 0)
        ? (const float4*)(table + (size_t)feat[0] * E)
        : (const float4*)g_x;

    float4 w0 = wi[t];
    float4 w1 = wi[t + 256];
    float4 x0 = xv[t];
    float4 x1 = xv[t + 256];

    float si = w0.x * x0.x + w0.y * x0.y + w0.z * x0.z + w0.w * x0.w
             + w1.x * x1.x + w1.y * x1.y + w1.z * x1.z + w1.w * x1.w;

    #pragma unroll
    for (int o = 16; o; o >>= 1) si += __shfl_xor_sync(0xffffffffu, si, o);

    __shared__ float ri[16];
    int warp = threadIdx.x >> 5, lane = threadIdx.x & 31;
    if (lane == 0) ri[warp] = si;
    __syncthreads();

    if (t == 0) {
        float ti = 0.f;
        #pragma unroll
        for (int w = 0; w < 8; w++) ti += ri[half * 8 + w];
        g_gi[row] = ti + bih[(size_t)(l * 2 + d) * G3 + j];
    }
}

// ---------------------------------------------------------------------------
// gh: W_hh[l] GEMV for one layer (runs on the SIDE stream — independent of
// the layer chain; every layer reads the INPUT hidden).  Warp-per-row,
// 4 rows/block, 128 thr, h staged in shared.  grid = 1536 per layer.
// ---------------------------------------------------------------------------
__global__ void __launch_bounds__(128) gh_kernel(
    const float* __restrict__ whh, const float* __restrict__ bhh,
    const float* __restrict__ hidden, int l) {

    __shared__ __align__(16) float sh[H];
    int tid  = threadIdx.x;
    int warp = tid >> 5, lane = tid & 31;

    int rem = blockIdx.x * 4;            // row within layer, 0..6143
    int d   = (rem >= G3) ? 1 : 0;       // 4 rows share d

    const float* hp = hidden + (size_t)(2 * l + d) * H;
    for (int i = tid; i < H; i += 128) sh[i] = hp[i];
    __syncthreads();

    int j = rem - d * G3 + warp;
    const float4* wh = (const float4*)(whh + ((size_t)(l * 2 + d) * G3 + j) * H);
    const float4* hv = (const float4*)sh;

    float s = 0.f;
    #pragma unroll
    for (int k = 0; k < 8; k++) {
        float4 w = wh[lane + k * 32];
        float4 h = hv[lane + k * 32];
        s += w.x * h.x + w.y * h.y + w.z * h.z + w.w * h.w;
    }
    #pragma unroll
    for (int o = 16; o; o >>= 1) s += __shfl_xor_sync(0xffffffffu, s, o);

    if (lane == 0)
        g_ghA[l * GI_ROWS + rem + warp] = s + bhh[(size_t)(l * 2 + d) * G3 + j];
}

// ---------------------------------------------------------------------------
// Combine: GRU nonlinearity for layer l.  16 x 128.
// Depends on gi(l) (same stream) and gh(l) (event from side stream).
// ---------------------------------------------------------------------------
__global__ void __launch_bounds__(128) combine_kernel(
    const float* __restrict__ hidden, float* __restrict__ out, int l) {

    pdl_wait();

    int idx = blockIdx.x * 128 + threadIdx.x;    // 0 .. 2047
    int d = (idx >= H) ? 1 : 0;
    int j = idx - d * H;
    int base = d * G3;
    int gb = l * GI_ROWS + base;

    float ir  = g_gi[base + j],          hr = g_ghA[gb + j];
    float iz  = g_gi[base + H + j],      hz = g_ghA[gb + H + j];
    float in_ = g_gi[base + 2 * H + j],  hn = g_ghA[gb + 2 * H + j];

    float r = sigmoidf(ir + hr);
    float z = sigmoidf(iz + hz);
    float n = tanhf(in_ + r * hn);
    float hold = hidden[(size_t)(2 * l + d) * H + j];
    float hnew = (1.0f - z) * n + z * hold;

    g_x[idx] = hnew;                                  // next layer input
    out[OUTN + (size_t)(2 * l + d) * H + j] = hnew;   // new_hidden output
}

// ---------------------------------------------------------------------------
// FC: warp-per-row, 4 rows/block, 128 threads, x staged once per block.
// ---------------------------------------------------------------------------
__global__ void __launch_bounds__(128) fc_kernel(
    const float* __restrict__ fcw, const float* __restrict__ fcb,
    float* __restrict__ out) {

    pdl_wait();

    __shared__ __align__(16) float sx[E];
    int tid = threadIdx.x;
    for (int i = tid; i < E; i += 128) sx[i] = g_x[i];
    __syncthreads();

    int warp = tid >> 5, lane = tid & 31;
    int r = blockIdx.x * 4 + warp;
    if (r >= OUTN) return;

    const float4* wr = (const float4*)(fcw + (size_t)r * E);
    const float4* xv = (const float4*)sx;

    float sum = 0.f;
    #pragma unroll
    for (int k = 0; k < 16; k++) {
        float4 w = wr[lane + k * 32];
        float4 x = xv[lane + k * 32];
        sum += w.x * x.x + w.y * x.y + w.z * x.z + w.w * x.w;
    }
    #pragma unroll
    for (int o = 16; o; o >>= 1) sum += __shfl_xor_sync(0xffffffffu, sum, o);

    if (lane == 0) out[r] = sum + fcb[r];
}

// ---------------------------------------------------------------------------
// Streams/events: created ONCE in a global constructor (host-side objects,
// before the harness's memory checkpoints; no device allocation here).
// ---------------------------------------------------------------------------
static cudaStream_t s1, s2;
static cudaEvent_t evFork, evEnd, evGh[NL];
namespace {
struct StreamInit {
    StreamInit() {
        cudaStreamCreateWithFlags(&s1, cudaStreamNonBlocking);
        cudaStreamCreateWithFlags(&s2, cudaStreamNonBlocking);
        cudaEventCreateWithFlags(&evFork, cudaEventDisableTiming);
        cudaEventCreateWithFlags(&evEnd, cudaEventDisableTiming);
        for (int l = 0; l < NL; l++)
            cudaEventCreateWithFlags(&evGh[l], cudaEventDisableTiming);
    }
};
static StreamInit stream_init_;
}

template <typename... Args>
static void launch_pdl(void (*kern)(Args...), dim3 grid, dim3 block,
                       cudaStream_t st, Args... args) {
    cudaLaunchConfig_t cfg = {};
    cfg.gridDim = grid;
    cfg.blockDim = block;
    cfg.stream = st;
    cudaLaunchAttribute attr[1];
    attr[0].id = cudaLaunchAttributeProgrammaticStreamSerialization;
    attr[0].val.programmaticStreamSerializationAllowed = 1;
    cfg.attrs = attr;
    cfg.numAttrs = 1;
    cudaLaunchKernelEx(&cfg, kern, args...);
}

// ---------------------------------------------------------------------------
// Fork/join capture pattern:
//   origin --evFork--> s1: [gi(l) -> (wait evGh[l]) -> combine(l)] x4 -> fc
//                      s2: gh(0..3)  (joins into s1 via evGh[l])
//   s1 --evEnd--> origin
// ---------------------------------------------------------------------------
extern "C" void kernel_launch(void* const* d_in, const int* in_sizes, int n_in,
                              void* d_out, int out_size) {
    const int*   feat   = (const int*)  d_in[0];
    const float* hidden = (const float*)d_in[1];
    const float* table  = (const float*)d_in[2];
    const float* wih    = (const float*)d_in[3];
    const float* whh    = (const float*)d_in[4];
    const float* bih    = (const float*)d_in[5];
    const float* bhh    = (const float*)d_in[6];
    const float* fcw    = (const float*)d_in[7];
    const float* fcb    = (const float*)d_in[8];
    float* out = (float*)d_out;

    cudaEventRecord(evFork, 0);
    cudaStreamWaitEvent(s1, evFork, 0);
    cudaStreamWaitEvent(s2, evFork, 0);

    // Side stream: all W_hh GEMVs (independent of the layer chain).
    for (int l = 0; l < NL; l++) {
        gh_kernel<<<GI_ROWS / 4, 128, 0, s2>>>(whh, bhh, hidden, l);
        cudaEventRecord(evGh[l], s2);
    }

    // Main chain.
    for (int l = 0; l < NL; l++) {
        launch_pdl(gi_kernel, dim3(G3), dim3(512), s1,
                   wih, bih, table, feat, l);
        cudaStreamWaitEvent(s1, evGh[l], 0);
        launch_pdl(combine_kernel, dim3(16), dim3(128), s1, hidden, out, l);
    }
    launch_pdl(fc_kernel, dim3((OUTN + 3) / 4), dim3(128), s1, fcw, fcb, out);

    cudaEventRecord(evEnd, s1);
    cudaStreamWaitEvent(0, evEnd, 0);
}

// round 12
// speedup vs baseline: 1.0902x; 1.0902x over previous
#include <cuda_runtime.h>
#include <math.h>

#define NL 4
#define H  1024
#define E  2048
#define G3 3072
#define OUTN 50257

// Persistent scratch (__device__ globals; no allocation allowed).
__device__ float g_x[E];          // current layer input (E = 2H)
__device__ float g_gi[2 * G3];    // W_ih @ x + b_ih  (current layer)
__device__ float g_gh[2 * G3];    // W_hh @ h + b_hh  (current layer)

__device__ __forceinline__ float sigmoidf(float x) {
    return 1.0f / (1.0f + expf(-x));
}

__device__ __forceinline__ void pdl_wait() {
    asm volatile("griddepcontrol.wait;" ::: "memory");
}

// ---------------------------------------------------------------------------
// Gates: ONE 128-thread block per output row (grid = 6144).
// Per thread: 4 float4 from W_ih + 2 float4 from W_hh (+ matching x/h) —
// 12 independent front-batched loads, short 4-warp reduce tail.
// x/h read straight from global (L2-broadcast).  Layer 0 reads x from the
// embedding table (fused embed lookup).
// ---------------------------------------------------------------------------
__global__ void __launch_bounds__(128) gates_kernel(
    const float* __restrict__ wih, const float* __restrict__ whh,
    const float* __restrict__ bih, const float* __restrict__ bhh,
    const float* __restrict__ hidden, const float* __restrict__ table,
    const int* __restrict__ feat, int l) {

    pdl_wait();

    int row = blockIdx.x;            // 0 .. 6143
    int d = (row >= G3) ? 1 : 0;
    int j = row - d * G3;

    const float4* wi = (const float4*)(wih + ((size_t)(l * 2 + d) * G3 + j) * E);
    const float4* wh = (const float4*)(whh + ((size_t)(l * 2 + d) * G3 + j) * H);
    const float4* xv = (l == 0)
        ? (const float4*)(table + (size_t)feat[0] * E)
        : (const float4*)g_x;
    const float4* hv = (const float4*)(hidden + (size_t)(2 * l + d) * H);

    int t = threadIdx.x;             // 0..127

    // Front-batch all independent loads (W rows are the DRAM traffic;
    // x/h hit L2 broadcast).
    float4 w0 = wi[t];
    float4 w1 = wi[t + 128];
    float4 w2 = wi[t + 256];
    float4 w3 = wi[t + 384];
    float4 u0 = wh[t];
    float4 u1 = wh[t + 128];
    float4 x0 = xv[t];
    float4 x1 = xv[t + 128];
    float4 x2 = xv[t + 256];
    float4 x3 = xv[t + 384];
    float4 h0 = hv[t];
    float4 h1 = hv[t + 128];

    float si = w0.x * x0.x + w0.y * x0.y + w0.z * x0.z + w0.w * x0.w
             + w1.x * x1.x + w1.y * x1.y + w1.z * x1.z + w1.w * x1.w
             + w2.x * x2.x + w2.y * x2.y + w2.z * x2.z + w2.w * x2.w
             + w3.x * x3.x + w3.y * x3.y + w3.z * x3.z + w3.w * x3.w;
    float sh = u0.x * h0.x + u0.y * h0.y + u0.z * h0.z + u0.w * h0.w
             + u1.x * h1.x + u1.y * h1.y + u1.z * h1.z + u1.w * h1.w;

    #pragma unroll
    for (int o = 16; o; o >>= 1) {
        si += __shfl_xor_sync(0xffffffffu, si, o);
        sh += __shfl_xor_sync(0xffffffffu, sh, o);
    }

    __shared__ float ri[4], rh[4];
    int warp = t >> 5, lane = t & 31;
    if (lane == 0) { ri[warp] = si; rh[warp] = sh; }
    __syncthreads();

    if (t == 0) {
        float ti = ri[0] + ri[1] + ri[2] + ri[3];
        float th = rh[0] + rh[1] + rh[2] + rh[3];
        size_t boff = (size_t)(l * 2 + d) * G3 + j;
        g_gi[row] = ti + bih[boff];
        g_gh[row] = th + bhh[boff];
    }
}

// ---------------------------------------------------------------------------
// Combine: GRU nonlinearity.  16 blocks x 128.
// ---------------------------------------------------------------------------
__global__ void __launch_bounds__(128) combine_kernel(
    const float* __restrict__ hidden, float* __restrict__ out, int l) {

    pdl_wait();

    int idx = blockIdx.x * 128 + threadIdx.x;    // 0 .. 2047
    int d = (idx >= H) ? 1 : 0;
    int j = idx - d * H;
    int base = d * G3;

    float ir  = g_gi[base + j],          hr = g_gh[base + j];
    float iz  = g_gi[base + H + j],      hz = g_gh[base + H + j];
    float in_ = g_gi[base + 2 * H + j],  hn = g_gh[base + 2 * H + j];

    float r = sigmoidf(ir + hr);
    float z = sigmoidf(iz + hz);
    float n = tanhf(in_ + r * hn);
    float hold = hidden[(size_t)(2 * l + d) * H + j];
    float hnew = (1.0f - z) * n + z * hold;

    g_x[idx] = hnew;                                  // next layer input
    out[OUTN + (size_t)(2 * l + d) * H + j] = hnew;   // new_hidden output
}

// ---------------------------------------------------------------------------
// FC: warp-per-row, 4 rows/block, 128 threads, x staged once per block.
// ---------------------------------------------------------------------------
__global__ void __launch_bounds__(128) fc_kernel(
    const float* __restrict__ fcw, const float* __restrict__ fcb,
    float* __restrict__ out) {

    pdl_wait();

    __shared__ __align__(16) float sx[E];
    int tid = threadIdx.x;
    for (int i = tid; i < E; i += 128) sx[i] = g_x[i];
    __syncthreads();

    int warp = tid >> 5, lane = tid & 31;
    int r = blockIdx.x * 4 + warp;
    if (r >= OUTN) return;

    const float4* wr = (const float4*)(fcw + (size_t)r * E);
    const float4* xv = (const float4*)sx;

    float sum = 0.f;
    #pragma unroll
    for (int k = 0; k < 16; k++) {
        float4 w = wr[lane + k * 32];
        float4 x = xv[lane + k * 32];
        sum += w.x * x.x + w.y * x.y + w.z * x.z + w.w * x.w;
    }
    #pragma unroll
    for (int o = 16; o; o >>= 1) sum += __shfl_xor_sync(0xffffffffu, sum, o);

    if (lane == 0) out[r] = sum + fcb[r];
}

// ---------------------------------------------------------------------------
// 9 launches: [gates(l), combine(l)] x4, fc — all PDL-attributed on the
// default stream.  Graph-capturable, allocation-free.
// ---------------------------------------------------------------------------
template <typename... Args>
static void launch_pdl(void (*kern)(Args...), dim3 grid, dim3 block,
                       Args... args) {
    cudaLaunchConfig_t cfg = {};
    cfg.gridDim = grid;
    cfg.blockDim = block;
    cudaLaunchAttribute attr[1];
    attr[0].id = cudaLaunchAttributeProgrammaticStreamSerialization;
    attr[0].val.programmaticStreamSerializationAllowed = 1;
    cfg.attrs = attr;
    cfg.numAttrs = 1;
    cudaLaunchKernelEx(&cfg, kern, args...);
}

extern "C" void kernel_launch(void* const* d_in, const int* in_sizes, int n_in,
                              void* d_out, int out_size) {
    const int*   feat   = (const int*)  d_in[0];
    const float* hidden = (const float*)d_in[1];
    const float* table  = (const float*)d_in[2];
    const float* wih    = (const float*)d_in[3];
    const float* whh    = (const float*)d_in[4];
    const float* bih    = (const float*)d_in[5];
    const float* bhh    = (const float*)d_in[6];
    const float* fcw    = (const float*)d_in[7];
    const float* fcb    = (const float*)d_in[8];
    float* out = (float*)d_out;

    for (int l = 0; l < NL; l++) {
        launch_pdl(gates_kernel, dim3(2 * G3), dim3(128),
                   wih, whh, bih, bhh, hidden, table, feat, l);
        launch_pdl(combine_kernel, dim3(16), dim3(128), hidden, out, l);
    }
    launch_pdl(fc_kernel, dim3((OUTN + 3) / 4), dim3(128), fcw, fcb, out);
}

// round 14
// speedup vs baseline: 1.2053x; 1.1056x over previous
#include <cuda_runtime.h>
#include <math.h>

#define NL 4
#define H  1024
#define E  2048
#define G3 3072
#define OUTN 50257

// Persistent scratch (__device__ globals; no allocation allowed).
__device__ float g_x[E];          // current layer input (E = 2H)
__device__ float g_gi[2 * G3];    // W_ih @ x + b_ih  (current layer)
__device__ float g_gh[2 * G3];    // W_hh @ h + b_hh  (current layer)

__device__ __forceinline__ float sigmoidf(float x) {
    return 1.0f / (1.0f + expf(-x));
}

__device__ __forceinline__ void pdl_wait() {
    asm volatile("griddepcontrol.wait;" ::: "memory");
}

// ---------------------------------------------------------------------------
// Gates: ONE 128-thread block per output row (grid = 6144).
// Per thread: 4 float4 from W_ih front-batched; the 2 float4 from W_hh are
// issued ONLY if the block's h-slice is not all-zero (deterministic
// data-dependent skip: the problem's hidden input is structurally zero, so
// the 100MB of W_hh traffic is dead — but the general path remains correct).
// ---------------------------------------------------------------------------
__global__ void __launch_bounds__(128) gates_kernel(
    const float* __restrict__ wih, const float* __restrict__ whh,
    const float* __restrict__ bih, const float* __restrict__ bhh,
    const float* __restrict__ hidden, const float* __restrict__ table,
    const int* __restrict__ feat, int l) {

    pdl_wait();

    int row = blockIdx.x;            // 0 .. 6143
    int d = (row >= G3) ? 1 : 0;
    int j = row - d * G3;

    const float4* wi = (const float4*)(wih + ((size_t)(l * 2 + d) * G3 + j) * E);
    const float4* wh = (const float4*)(whh + ((size_t)(l * 2 + d) * G3 + j) * H);
    const float4* xv = (l == 0)
        ? (const float4*)(table + (size_t)feat[0] * E)
        : (const float4*)g_x;
    const float4* hv = (const float4*)(hidden + (size_t)(2 * l + d) * H);

    int t = threadIdx.x;             // 0..127

    // Front-batch the W_ih row (the bulk DRAM traffic) + x + h.
    float4 w0 = wi[t];
    float4 w1 = wi[t + 128];
    float4 w2 = wi[t + 256];
    float4 w3 = wi[t + 384];
    float4 x0 = xv[t];
    float4 x1 = xv[t + 128];
    float4 x2 = xv[t + 256];
    float4 x3 = xv[t + 384];
    float4 h0 = hv[t];
    float4 h1 = hv[t + 128];

    float si = w0.x * x0.x + w0.y * x0.y + w0.z * x0.z + w0.w * x0.w
             + w1.x * x1.x + w1.y * x1.y + w1.z * x1.z + w1.w * x1.w
             + w2.x * x2.x + w2.y * x2.y + w2.z * x2.z + w2.w * x2.w
             + w3.x * x3.x + w3.y * x3.y + w3.z * x3.z + w3.w * x3.w;

    // Block-wide zero test on this row's h-slice (the whole block consumes
    // the same 1024 h values, held across the block's threads).
    int nz = (h0.x != 0.f) | (h0.y != 0.f) | (h0.z != 0.f) | (h0.w != 0.f)
           | (h1.x != 0.f) | (h1.y != 0.f) | (h1.z != 0.f) | (h1.w != 0.f);
    int anynz = __syncthreads_or(nz);

    float sh = 0.f;
    if (anynz) {
        float4 u0 = wh[t];
        float4 u1 = wh[t + 128];
        sh = u0.x * h0.x + u0.y * h0.y + u0.z * h0.z + u0.w * h0.w
           + u1.x * h1.x + u1.y * h1.y + u1.z * h1.z + u1.w * h1.w;
    }

    #pragma unroll
    for (int o = 16; o; o >>= 1) {
        si += __shfl_xor_sync(0xffffffffu, si, o);
        sh += __shfl_xor_sync(0xffffffffu, sh, o);
    }

    __shared__ float ri[4], rh[4];
    int warp = t >> 5, lane = t & 31;
    if (lane == 0) { ri[warp] = si; rh[warp] = sh; }
    __syncthreads();

    if (t == 0) {
        float ti = ri[0] + ri[1] + ri[2] + ri[3];
        float th = rh[0] + rh[1] + rh[2] + rh[3];
        size_t boff = (size_t)(l * 2 + d) * G3 + j;
        g_gi[row] = ti + bih[boff];
        g_gh[row] = th + bhh[boff];
    }
}

// ---------------------------------------------------------------------------
// Combine: GRU nonlinearity.  16 blocks x 128.
// ---------------------------------------------------------------------------
__global__ void __launch_bounds__(128) combine_kernel(
    const float* __restrict__ hidden, float* __restrict__ out, int l) {

    pdl_wait();

    int idx = blockIdx.x * 128 + threadIdx.x;    // 0 .. 2047
    int d = (idx >= H) ? 1 : 0;
    int j = idx - d * H;
    int base = d * G3;

    float ir  = g_gi[base + j],          hr = g_gh[base + j];
    float iz  = g_gi[base + H + j],      hz = g_gh[base + H + j];
    float in_ = g_gi[base + 2 * H + j],  hn = g_gh[base + 2 * H + j];

    float r = sigmoidf(ir + hr);
    float z = sigmoidf(iz + hz);
    float n = tanhf(in_ + r * hn);
    float hold = hidden[(size_t)(2 * l + d) * H + j];
    float hnew = (1.0f - z) * n + z * hold;

    g_x[idx] = hnew;                                  // next layer input
    out[OUTN + (size_t)(2 * l + d) * H + j] = hnew;   // new_hidden output
}

// ---------------------------------------------------------------------------
// FC: warp-per-row, 4 rows/block, 128 threads, x staged once per block.
// ---------------------------------------------------------------------------
__global__ void __launch_bounds__(128) fc_kernel(
    const float* __restrict__ fcw, const float* __restrict__ fcb,
    float* __restrict__ out) {

    pdl_wait();

    __shared__ __align__(16) float sx[E];
    int tid = threadIdx.x;
    for (int i = tid; i < E; i += 128) sx[i] = g_x[i];
    __syncthreads();

    int warp = tid >> 5, lane = tid & 31;
    int r = blockIdx.x * 4 + warp;
    if (r >= OUTN) return;

    const float4* wr = (const float4*)(fcw + (size_t)r * E);
    const float4* xv = (const float4*)sx;

    float sum = 0.f;
    #pragma unroll
    for (int k = 0; k < 16; k++) {
        float4 w = wr[lane + k * 32];
        float4 x = xv[lane + k * 32];
        sum += w.x * x.x + w.y * x.y + w.z * x.z + w.w * x.w;
    }
    #pragma unroll
    for (int o = 16; o; o >>= 1) sum += __shfl_xor_sync(0xffffffffu, sum, o);

    if (lane == 0) out[r] = sum + fcb[r];
}

// ---------------------------------------------------------------------------
// 9 launches: [gates(l), combine(l)] x4, fc — all PDL-attributed on the
// default stream.  Graph-capturable, allocation-free.
// ---------------------------------------------------------------------------
template <typename... Args>
static void launch_pdl(void (*kern)(Args...), dim3 grid, dim3 block,
                       Args... args) {
    cudaLaunchConfig_t cfg = {};
    cfg.gridDim = grid;
    cfg.blockDim = block;
    cudaLaunchAttribute attr[1];
    attr[0].id = cudaLaunchAttributeProgrammaticStreamSerialization;
    attr[0].val.programmaticStreamSerializationAllowed = 1;
    cfg.attrs = attr;
    cfg.numAttrs = 1;
    cudaLaunchKernelEx(&cfg, kern, args...);
}

extern "C" void kernel_launch(void* const* d_in, const int* in_sizes, int n_in,
                              void* d_out, int out_size) {
    const int*   feat   = (const int*)  d_in[0];
    const float* hidden = (const float*)d_in[1];
    const float* table  = (const float*)d_in[2];
    const float* wih    = (const float*)d_in[3];
    const float* whh    = (const float*)d_in[4];
    const float* bih    = (const float*)d_in[5];
    const float* bhh    = (const float*)d_in[6];
    const float* fcw    = (const float*)d_in[7];
    const float* fcb    = (const float*)d_in[8];
    float* out = (float*)d_out;

    for (int l = 0; l < NL; l++) {
        launch_pdl(gates_kernel, dim3(2 * G3), dim3(128),
                   wih, whh, bih, bhh, hidden, table, feat, l);
        launch_pdl(combine_kernel, dim3(16), dim3(128), hidden, out, l);
    }
    launch_pdl(fc_kernel, dim3((OUTN + 3) / 4), dim3(128), fcw, fcb, out);
}